// round 13
// baseline (speedup 1.0000x reference)
#include <cuda_runtime.h>
#include <cuda_fp16.h>
#include <cstdint>

#define NN  100000
#define NE  1600000
#define D   128
#define CAP 64   // slots per node; overflow handled exactly via side list

__device__ __half g_h0[(size_t)NN * D];    // gathered features, fp16
__device__ __half g_xh[(size_t)NN * D];    // x converted to fp16
__device__ __half g_W1t[D * D];            // W1^T fp16, [n][k]
__device__ __half g_W2t[D * D];            // W2^T fp16, [n][k]
__device__ int    g_cnt[NN];
__device__ int    g_slot[(size_t)NN * CAP];
__device__ int    g_ovf_n;
__device__ int2   g_ovf[NE];

// ---------------------------------------------------------------------------
// Kernel 1: prep = convert x->fp16 (blocks [0,n_conv)) + zero counters (tail)
// ---------------------------------------------------------------------------
__global__ __launch_bounds__(256)
void prep_kernel(const float* __restrict__ x, int n8, int n_conv, int n_nodes) {
    if ((int)blockIdx.x < n_conv) {
        int i = blockIdx.x * 256 + threadIdx.x;
        if (i >= n8) return;
        const float4* x4 = (const float4*)x;
        float4 v0 = __ldg(x4 + (size_t)i * 2);
        float4 v1 = __ldg(x4 + (size_t)i * 2 + 1);
        __half2 h0 = __floats2half2_rn(v0.x, v0.y);
        __half2 h1 = __floats2half2_rn(v0.z, v0.w);
        __half2 h2 = __floats2half2_rn(v1.x, v1.y);
        __half2 h3 = __floats2half2_rn(v1.z, v1.w);
        uint4 o;
        o.x = *(uint32_t*)&h0; o.y = *(uint32_t*)&h1;
        o.z = *(uint32_t*)&h2; o.w = *(uint32_t*)&h3;
        ((uint4*)g_xh)[i] = o;
    } else {
        int i = (blockIdx.x - n_conv) * 256 + threadIdx.x;
        if (i < n_nodes) g_cnt[i] = 0;
        if (i == 0 && blockIdx.x == (unsigned)n_conv) g_ovf_n = 0;
    }
}

// ---------------------------------------------------------------------------
// Kernel 2: binned fill + weight transpose->fp16 (32 tail blocks)
// ---------------------------------------------------------------------------
__global__ __launch_bounds__(256)
void fill_kernel(const int* __restrict__ src,
                 const int* __restrict__ dst, int n_edges, int n_fill,
                 const float* __restrict__ W1, __half* __restrict__ W1t,
                 const float* __restrict__ W2, __half* __restrict__ W2t) {
    __shared__ float t[32][33];
    if (blockIdx.x >= (unsigned)n_fill) {
        int bid = blockIdx.x - n_fill;        // 0..31
        const float* W  = (bid & 16) ? W2 : W1;
        __half*      Wt = (bid & 16) ? W2t : W1t;
        int bx = (bid & 3) * 32, by = ((bid >> 2) & 3) * 32;
        int x = threadIdx.x & 31, y = threadIdx.x >> 5;   // (32,8)
#pragma unroll
        for (int i = 0; i < 32; i += 8)
            t[y + i][x] = W[(size_t)(by + y + i) * D + bx + x];
        __syncthreads();
#pragma unroll
        for (int i = 0; i < 32; i += 8)
            Wt[(size_t)(bx + y + i) * D + by + x] = __float2half_rn(t[x][y + i]);
        return;
    }
    int e = blockIdx.x * blockDim.x + threadIdx.x;
    if (e >= n_edges) return;
    int s = __ldg(src + e);
    int d = __ldg(dst + e);
    int p = atomicAdd(&g_cnt[d], 1);
    if (p < CAP) {
        g_slot[(size_t)d * CAP + p] = s;
    } else {
        int q = atomicAdd(&g_ovf_n, 1);
        g_ovf[q] = make_int2(s, d);
    }
}

// ---------------------------------------------------------------------------
// Kernel 3: gather, TWO nodes per warp (16 lanes per 256B fp16 row).
// One LDG.128 + one SHFL serves 2 edges. fp32 accumulate, fp16 h0 write.
// ---------------------------------------------------------------------------
__global__ __launch_bounds__(256)
void gather_kernel(const float* __restrict__ eps_p, int n_nodes) {
    int warp = (blockIdx.x * blockDim.x + threadIdx.x) >> 5;
    int lane = threadIdx.x & 31;
    int half = lane >> 4;              // which node of the pair
    int hl   = lane & 15;              // 16B chunk within row
    int node = warp * 2 + half;
    bool active = (node < n_nodes);
    if (warp * 2 >= n_nodes) return;

    float s = 1.0f + __ldg(eps_p);
    const uint4* xh4 = (const uint4*)g_xh;   // 8 halves per uint4, 16/row

    int cnt_full = active ? __ldg(&g_cnt[node]) : 0;
    int cnt = min(cnt_full, CAP);
    int cmax = max(cnt, __shfl_xor_sync(0xffffffffu, cnt, 16));

    float acc[8];
    if (active) {
        uint4 v = __ldg(xh4 + (size_t)node * 16 + hl);
        const __half2* hp = (const __half2*)&v;
#pragma unroll
        for (int q = 0; q < 4; q++) {
            float2 f = __half22float2(hp[q]);
            acc[2 * q]     = f.x * s;
            acc[2 * q + 1] = f.y * s;
        }
    } else {
#pragma unroll
        for (int q = 0; q < 8; q++) acc[q] = 0.f;
    }

    const int* slots = g_slot + (size_t)node * CAP;
    for (int b = 0; b < cmax; b += 16) {
        int idx = (b + hl < cnt) ? __ldg(slots + b + hl) : 0;
#pragma unroll 4
        for (int j = 0; j < 16; j++) {
            if (b + j >= cmax) break;
            int sj = __shfl_sync(0xffffffffu, idx, (half << 4) + j);
            if (b + j < cnt) {
                uint4 w = __ldg(xh4 + (size_t)sj * 16 + hl);
                const __half2* wp = (const __half2*)&w;
#pragma unroll
                for (int q = 0; q < 4; q++) {
                    float2 f = __half22float2(wp[q]);
                    acc[2 * q]     += f.x;
                    acc[2 * q + 1] += f.y;
                }
            }
        }
    }
    if (cnt_full > CAP) {   // exact overflow path (empty in practice)
        int n = g_ovf_n;
        for (int e = 0; e < n; e++) {
            int2 sd = g_ovf[e];
            if (sd.y == node) {
                uint4 w = __ldg(xh4 + (size_t)sd.x * 16 + hl);
                const __half2* wp = (const __half2*)&w;
#pragma unroll
                for (int q = 0; q < 4; q++) {
                    float2 f = __half22float2(wp[q]);
                    acc[2 * q]     += f.x;
                    acc[2 * q + 1] += f.y;
                }
            }
        }
    }
    if (active) {
        uint4 o;
        __half2 h0 = __floats2half2_rn(acc[0], acc[1]);
        __half2 h1 = __floats2half2_rn(acc[2], acc[3]);
        __half2 h2 = __floats2half2_rn(acc[4], acc[5]);
        __half2 h3 = __floats2half2_rn(acc[6], acc[7]);
        o.x = *(uint32_t*)&h0; o.y = *(uint32_t*)&h1;
        o.z = *(uint32_t*)&h2; o.w = *(uint32_t*)&h3;
        ((uint4*)g_h0)[(size_t)node * 16 + hl] = o;
    }
}

// ---------------------------------------------------------------------------
// fp16 mma.sync m16n8k16 (fp32 accumulate)
// ---------------------------------------------------------------------------
__device__ __forceinline__ void mma_f16(float* c, const uint32_t* a, const uint32_t* b) {
    asm volatile(
        "mma.sync.aligned.m16n8k16.row.col.f32.f16.f16.f32 "
        "{%0,%1,%2,%3}, {%4,%5,%6,%7}, {%8,%9}, {%0,%1,%2,%3};"
        : "+f"(c[0]), "+f"(c[1]), "+f"(c[2]), "+f"(c[3])
        : "r"(a[0]), "r"(a[1]), "r"(a[2]), "r"(a[3]),
          "r"(b[0]), "r"(b[1]));
}

#define HS 136            // halves per SMEM row (128 + 8 pad)
#define HW (HS / 2)       // 68 uint32 words per row
#define TM 128            // CTA rows

// ---------------------------------------------------------------------------
// Kernel 4: fused MLP, all-fp16 operands (R12 winner, unchanged).
// CTA 128x128, 8 warps 2(M)x4(N), warp tile 64x32, m16n8k16.
// SMEM 68 KB -> 2 CTAs/SM.
// ---------------------------------------------------------------------------
__global__ __launch_bounds__(256, 2)
void fused_mlp_kernel(const __half* __restrict__ A,
                      const __half* __restrict__ W1t,
                      const float* __restrict__ b1,
                      const __half* __restrict__ W2t,
                      const float* __restrict__ b2,
                      float* __restrict__ C, int M) {
    extern __shared__ __half smem16[];
    __half* As16 = smem16;                  // [128][136]
    __half* Bs16 = smem16 + TM * HS;        // [128][136]
    uint32_t* Asw = (uint32_t*)As16;
    uint32_t* Bsw = (uint32_t*)Bs16;

    const int tid = threadIdx.x;
    const int wid = tid >> 5;
    const int lid = tid & 31;
    const int wm = wid >> 2;            // 0..1 -> 64-row slab
    const int wn = wid & 3;             // 0..3 -> 32-col slab
    const int gid = lid >> 2;
    const int tig = lid & 3;
    const int row0 = blockIdx.x * TM;

    // ---- load A tile ----
#pragma unroll
    for (int it = 0; it < 8; it++) {
        int idx = tid + it * 256;          // 0..2047 uint4s
        int r = idx >> 4;
        int c8 = idx & 15;
        uint4 va = make_uint4(0u, 0u, 0u, 0u);
        int grow = row0 + r;
        if (grow < M) va = __ldg((const uint4*)(A + (size_t)grow * 128) + c8);
        *(uint4*)&As16[r * HS + c8 * 8] = va;
    }
    // ---- load W1 ----
#pragma unroll
    for (int it = 0; it < 8; it++) {
        int idx = tid + it * 256;
        int r = idx >> 4;
        int c8 = idx & 15;
        uint4 vb = __ldg((const uint4*)(W1t + (size_t)r * 128) + c8);
        *(uint4*)&Bs16[r * HS + c8 * 8] = vb;
    }
    __syncthreads();

    float acc[4][4][4];
#pragma unroll
    for (int mt = 0; mt < 4; mt++)
#pragma unroll
        for (int nt = 0; nt < 4; nt++)
#pragma unroll
            for (int q = 0; q < 4; q++) acc[mt][nt][q] = 0.0f;

    // ---- mainloop 1 (W1): 8 k-steps of 16 ----
#pragma unroll
    for (int ks = 0; ks < 8; ks++) {
        int kw = ks * 8;
        uint32_t bfr[4][2];
#pragma unroll
        for (int nt = 0; nt < 4; nt++) {
            int n = wn * 32 + nt * 8 + gid;
            bfr[nt][0] = Bsw[n * HW + kw + tig];
            bfr[nt][1] = Bsw[n * HW + kw + tig + 4];
        }
#pragma unroll
        for (int mt = 0; mt < 4; mt++) {
            int r = wm * 64 + mt * 16 + gid;
            uint32_t afr[4];
            afr[0] = Asw[r * HW + kw + tig];
            afr[1] = Asw[(r + 8) * HW + kw + tig];
            afr[2] = Asw[r * HW + kw + tig + 4];
            afr[3] = Asw[(r + 8) * HW + kw + tig + 4];
#pragma unroll
            for (int nt = 0; nt < 4; nt++)
                mma_f16(acc[mt][nt], afr, bfr[nt]);
        }
    }
    __syncthreads();

    // ---- relu(acc + b1) back into As as half2 ----
#pragma unroll
    for (int mt = 0; mt < 4; mt++) {
        int r0 = wm * 64 + mt * 16 + gid;
#pragma unroll
        for (int nt = 0; nt < 4; nt++) {
            int c0 = wn * 32 + nt * 8 + 2 * tig;
            float bb0 = __ldg(b1 + c0), bb1 = __ldg(b1 + c0 + 1);
            __half2 v0 = __floats2half2_rn(fmaxf(acc[mt][nt][0] + bb0, 0.f),
                                           fmaxf(acc[mt][nt][1] + bb1, 0.f));
            __half2 v1 = __floats2half2_rn(fmaxf(acc[mt][nt][2] + bb0, 0.f),
                                           fmaxf(acc[mt][nt][3] + bb1, 0.f));
            Asw[r0 * HW + (c0 >> 1)] = *(uint32_t*)&v0;
            Asw[(r0 + 8) * HW + (c0 >> 1)] = *(uint32_t*)&v1;
        }
    }
    // ---- reload Bs = W2 ----
#pragma unroll
    for (int it = 0; it < 8; it++) {
        int idx = tid + it * 256;
        int r = idx >> 4;
        int c8 = idx & 15;
        uint4 vb = __ldg((const uint4*)(W2t + (size_t)r * 128) + c8);
        *(uint4*)&Bs16[r * HS + c8 * 8] = vb;
    }
    __syncthreads();

    // ---- mainloop 2 (W2) ----
#pragma unroll
    for (int mt = 0; mt < 4; mt++)
#pragma unroll
        for (int nt = 0; nt < 4; nt++)
#pragma unroll
            for (int q = 0; q < 4; q++) acc[mt][nt][q] = 0.0f;

#pragma unroll
    for (int ks = 0; ks < 8; ks++) {
        int kw = ks * 8;
        uint32_t bfr[4][2];
#pragma unroll
        for (int nt = 0; nt < 4; nt++) {
            int n = wn * 32 + nt * 8 + gid;
            bfr[nt][0] = Bsw[n * HW + kw + tig];
            bfr[nt][1] = Bsw[n * HW + kw + tig + 4];
        }
#pragma unroll
        for (int mt = 0; mt < 4; mt++) {
            int r = wm * 64 + mt * 16 + gid;
            uint32_t afr[4];
            afr[0] = Asw[r * HW + kw + tig];
            afr[1] = Asw[(r + 8) * HW + kw + tig];
            afr[2] = Asw[r * HW + kw + tig + 4];
            afr[3] = Asw[(r + 8) * HW + kw + tig + 4];
#pragma unroll
            for (int nt = 0; nt < 4; nt++)
                mma_f16(acc[mt][nt], afr, bfr[nt]);
        }
    }

    // ---- epilogue to global (fp32) ----
#pragma unroll
    for (int mt = 0; mt < 4; mt++) {
        int r0 = row0 + wm * 64 + mt * 16 + gid;
        int r1 = r0 + 8;
#pragma unroll
        for (int nt = 0; nt < 4; nt++) {
            int c0 = wn * 32 + nt * 8 + 2 * tig;
            float bb0 = __ldg(b2 + c0), bb1 = __ldg(b2 + c0 + 1);
            float2 v0 = make_float2(acc[mt][nt][0] + bb0, acc[mt][nt][1] + bb1);
            float2 v1 = make_float2(acc[mt][nt][2] + bb0, acc[mt][nt][3] + bb1);
            if (r0 < M) *(float2*)(C + (size_t)r0 * 128 + c0) = v0;
            if (r1 < M) *(float2*)(C + (size_t)r1 * 128 + c0) = v1;
        }
    }
}

// ---------------------------------------------------------------------------
extern "C" void kernel_launch(void* const* d_in, const int* in_sizes, int n_in,
                              void* d_out, int out_size) {
    const float* x   = (const float*)d_in[0];
    const int*   ei  = (const int*)d_in[1];
    const float* W1  = (const float*)d_in[2];
    const float* b1  = (const float*)d_in[3];
    const float* W2  = (const float*)d_in[4];
    const float* b2  = (const float*)d_in[5];
    const float* eps = (const float*)d_in[6];
    float*       out = (float*)d_out;

    const int n_nodes = in_sizes[0] / D;
    const int n_edges = in_sizes[1] / 2;
    const int* src = ei;
    const int* dst = ei + n_edges;

    __half *h0, *w1t, *w2t;
    cudaGetSymbolAddress((void**)&h0, g_h0);
    cudaGetSymbolAddress((void**)&w1t, g_W1t);
    cudaGetSymbolAddress((void**)&w2t, g_W2t);

    const int SMEM = 2 * TM * HS * (int)sizeof(__half);  // 69632
    cudaFuncSetAttribute(fused_mlp_kernel,
                         cudaFuncAttributeMaxDynamicSharedMemorySize, SMEM);

    int n8 = n_nodes * D / 8;
    int n_conv = (n8 + 255) / 256;
    int n_zero = (n_nodes + 255) / 256;
    prep_kernel<<<n_conv + n_zero, 256>>>(x, n8, n_conv, n_nodes);

    int n_fill = (n_edges + 255) / 256;
    fill_kernel<<<n_fill + 32, 256>>>(src, dst, n_edges, n_fill,
                                      W1, w1t, W2, w2t);

    int npairs = (n_nodes + 1) / 2;
    int gwarps = (npairs * 32 + 255) / 256;
    gather_kernel<<<gwarps, 256>>>(eps, n_nodes);

    int gblocks = (n_nodes + TM - 1) / TM;
    fused_mlp_kernel<<<gblocks, 256, SMEM>>>(h0, w1t, b1, w2t, b2, out, n_nodes);
}

// round 14
// speedup vs baseline: 1.0532x; 1.0532x over previous
#include <cuda_runtime.h>
#include <cuda_fp16.h>
#include <cstdint>

#define NN  100000
#define NE  1600000
#define D   128
#define CAP 32   // slots per node; overflow handled exactly via side list

__device__ __half g_h0[(size_t)NN * D];    // gathered features, fp16
__device__ __half g_xh[(size_t)NN * D];    // x converted to fp16
__device__ __half g_W1t[D * D];            // W1^T fp16, [n][k]
__device__ __half g_W2t[D * D];            // W2^T fp16, [n][k]
__device__ int    g_cnt[NN];
__device__ int    g_slot[(size_t)NN * CAP];
__device__ int    g_ovf_n;
__device__ int2   g_ovf[NE];

// ---------------------------------------------------------------------------
// Kernel 1: zero counters (tiny; must precede fill's atomics)
// ---------------------------------------------------------------------------
__global__ void zero_kernel(int n) {
    int i = blockIdx.x * blockDim.x + threadIdx.x;
    if (i < n) g_cnt[i] = 0;
    if (i == 0) g_ovf_n = 0;
}

// ---------------------------------------------------------------------------
// Kernel 2: combined work kernel, disjoint block ranges:
//   [0, n_conv)            : convert x -> fp16
//   [n_conv, n_conv+n_fill): binned edge fill
//   last 32 blocks         : weight transpose -> fp16
// All three independent once counters are zeroed.
// ---------------------------------------------------------------------------
__global__ __launch_bounds__(256)
void work_kernel(const float* __restrict__ x, int n8, int n_conv,
                 const int* __restrict__ src, const int* __restrict__ dst,
                 int n_edges, int n_fill,
                 const float* __restrict__ W1, __half* __restrict__ W1t,
                 const float* __restrict__ W2, __half* __restrict__ W2t) {
    __shared__ float t[32][33];
    int b = blockIdx.x;
    if (b < n_conv) {
        int i = b * 256 + threadIdx.x;
        if (i >= n8) return;
        const float4* x4 = (const float4*)x;
        float4 v0 = __ldg(x4 + (size_t)i * 2);
        float4 v1 = __ldg(x4 + (size_t)i * 2 + 1);
        __half2 h0 = __floats2half2_rn(v0.x, v0.y);
        __half2 h1 = __floats2half2_rn(v0.z, v0.w);
        __half2 h2 = __floats2half2_rn(v1.x, v1.y);
        __half2 h3 = __floats2half2_rn(v1.z, v1.w);
        uint4 o;
        o.x = *(uint32_t*)&h0; o.y = *(uint32_t*)&h1;
        o.z = *(uint32_t*)&h2; o.w = *(uint32_t*)&h3;
        ((uint4*)g_xh)[i] = o;
        return;
    }
    if (b < n_conv + n_fill) {
        int e = (b - n_conv) * 256 + threadIdx.x;
        if (e >= n_edges) return;
        int s = __ldg(src + e);
        int d = __ldg(dst + e);
        int p = atomicAdd(&g_cnt[d], 1);
        if (p < CAP) {
            g_slot[(size_t)d * CAP + p] = s;
        } else {
            int q = atomicAdd(&g_ovf_n, 1);
            g_ovf[q] = make_int2(s, d);
        }
        return;
    }
    // transpose tail: 32 blocks
    {
        int bid = b - n_conv - n_fill;        // 0..31
        const float* W  = (bid & 16) ? W2 : W1;
        __half*      Wt = (bid & 16) ? W2t : W1t;
        int bx = (bid & 3) * 32, by = ((bid >> 2) & 3) * 32;
        int xx = threadIdx.x & 31, y = threadIdx.x >> 5;   // (32,8)
#pragma unroll
        for (int i = 0; i < 32; i += 8)
            t[y + i][xx] = W[(size_t)(by + y + i) * D + bx + xx];
        __syncthreads();
#pragma unroll
        for (int i = 0; i < 32; i += 8)
            Wt[(size_t)(bx + y + i) * D + by + xx] = __float2half_rn(t[xx][y + i]);
    }
}

// ---------------------------------------------------------------------------
// Kernel 3: gather (R12 winner shape). One warp per node; fp16 reads,
// fp32 accumulate, fp16 h0 write. Per-lane 4 features = uint2 (8B).
// ---------------------------------------------------------------------------
__global__ __launch_bounds__(256)
void gather_kernel(const float* __restrict__ eps_p, int n_nodes) {
    int warp = (blockIdx.x * blockDim.x + threadIdx.x) >> 5;
    if (warp >= n_nodes) return;
    int lane = threadIdx.x & 31;

    int cnt_full = __ldg(&g_cnt[warp]);
    int cnt = min(cnt_full, CAP);
    float s = 1.0f + __ldg(eps_p);

    const uint2* xh2 = (const uint2*)g_xh;
    uint2 v = __ldg(xh2 + (size_t)warp * 32 + lane);
    float2 fa = __half22float2(*(__half2*)&v.x);
    float2 fb = __half22float2(*(__half2*)&v.y);
    float4 acc = make_float4(fa.x * s, fa.y * s, fb.x * s, fb.y * s);

    const int* slots = g_slot + (size_t)warp * CAP;
    for (int b = 0; b < cnt; b += 32) {
        int c = min(32, cnt - b);
        int idx = (lane < c) ? __ldg(slots + b + lane) : 0;
#pragma unroll 4
        for (int j = 0; j < c; j++) {
            int sj = __shfl_sync(0xffffffffu, idx, j);
            uint2 w = __ldg(xh2 + (size_t)sj * 32 + lane);
            float2 wa = __half22float2(*(__half2*)&w.x);
            float2 wb = __half22float2(*(__half2*)&w.y);
            acc.x += wa.x; acc.y += wa.y; acc.z += wb.x; acc.w += wb.y;
        }
    }
    if (cnt_full > CAP) {   // exact overflow path (rare)
        int n = g_ovf_n;
        for (int e = 0; e < n; e++) {
            int2 sd = g_ovf[e];
            if (sd.y == warp) {
                uint2 w = __ldg(xh2 + (size_t)sd.x * 32 + lane);
                float2 wa = __half22float2(*(__half2*)&w.x);
                float2 wb = __half22float2(*(__half2*)&w.y);
                acc.x += wa.x; acc.y += wa.y; acc.z += wb.x; acc.w += wb.y;
            }
        }
    }
    __half2 o0 = __floats2half2_rn(acc.x, acc.y);
    __half2 o1 = __floats2half2_rn(acc.z, acc.w);
    uint2 o;
    o.x = *(uint32_t*)&o0; o.y = *(uint32_t*)&o1;
    ((uint2*)g_h0)[(size_t)warp * 32 + lane] = o;
}

// ---------------------------------------------------------------------------
// fp16 mma.sync m16n8k16 (fp32 accumulate)
// ---------------------------------------------------------------------------
__device__ __forceinline__ void mma_f16(float* c, const uint32_t* a, const uint32_t* b) {
    asm volatile(
        "mma.sync.aligned.m16n8k16.row.col.f32.f16.f16.f32 "
        "{%0,%1,%2,%3}, {%4,%5,%6,%7}, {%8,%9}, {%0,%1,%2,%3};"
        : "+f"(c[0]), "+f"(c[1]), "+f"(c[2]), "+f"(c[3])
        : "r"(a[0]), "r"(a[1]), "r"(a[2]), "r"(a[3]),
          "r"(b[0]), "r"(b[1]));
}

#define HS 136            // halves per SMEM row (128 + 8 pad)
#define HW (HS / 2)       // 68 uint32 words per row
#define TM 128            // CTA rows

// ---------------------------------------------------------------------------
// Kernel 4: fused MLP, all-fp16 operands (R12 winner, unchanged).
// CTA 128x128, 8 warps 2(M)x4(N), warp tile 64x32, m16n8k16.
// SMEM 68 KB -> 2 CTAs/SM.
// ---------------------------------------------------------------------------
__global__ __launch_bounds__(256, 2)
void fused_mlp_kernel(const __half* __restrict__ A,
                      const __half* __restrict__ W1t,
                      const float* __restrict__ b1,
                      const __half* __restrict__ W2t,
                      const float* __restrict__ b2,
                      float* __restrict__ C, int M) {
    extern __shared__ __half smem16[];
    __half* As16 = smem16;                  // [128][136]
    __half* Bs16 = smem16 + TM * HS;        // [128][136]
    uint32_t* Asw = (uint32_t*)As16;
    uint32_t* Bsw = (uint32_t*)Bs16;

    const int tid = threadIdx.x;
    const int wid = tid >> 5;
    const int lid = tid & 31;
    const int wm = wid >> 2;            // 0..1 -> 64-row slab
    const int wn = wid & 3;             // 0..3 -> 32-col slab
    const int gid = lid >> 2;
    const int tig = lid & 3;
    const int row0 = blockIdx.x * TM;

    // ---- load A tile ----
#pragma unroll
    for (int it = 0; it < 8; it++) {
        int idx = tid + it * 256;
        int r = idx >> 4;
        int c8 = idx & 15;
        uint4 va = make_uint4(0u, 0u, 0u, 0u);
        int grow = row0 + r;
        if (grow < M) va = __ldg((const uint4*)(A + (size_t)grow * 128) + c8);
        *(uint4*)&As16[r * HS + c8 * 8] = va;
    }
    // ---- load W1 ----
#pragma unroll
    for (int it = 0; it < 8; it++) {
        int idx = tid + it * 256;
        int r = idx >> 4;
        int c8 = idx & 15;
        uint4 vb = __ldg((const uint4*)(W1t + (size_t)r * 128) + c8);
        *(uint4*)&Bs16[r * HS + c8 * 8] = vb;
    }
    __syncthreads();

    float acc[4][4][4];
#pragma unroll
    for (int mt = 0; mt < 4; mt++)
#pragma unroll
        for (int nt = 0; nt < 4; nt++)
#pragma unroll
            for (int q = 0; q < 4; q++) acc[mt][nt][q] = 0.0f;

    // ---- mainloop 1 (W1): 8 k-steps of 16 ----
#pragma unroll
    for (int ks = 0; ks < 8; ks++) {
        int kw = ks * 8;
        uint32_t bfr[4][2];
#pragma unroll
        for (int nt = 0; nt < 4; nt++) {
            int n = wn * 32 + nt * 8 + gid;
            bfr[nt][0] = Bsw[n * HW + kw + tig];
            bfr[nt][1] = Bsw[n * HW + kw + tig + 4];
        }
#pragma unroll
        for (int mt = 0; mt < 4; mt++) {
            int r = wm * 64 + mt * 16 + gid;
            uint32_t afr[4];
            afr[0] = Asw[r * HW + kw + tig];
            afr[1] = Asw[(r + 8) * HW + kw + tig];
            afr[2] = Asw[r * HW + kw + tig + 4];
            afr[3] = Asw[(r + 8) * HW + kw + tig + 4];
#pragma unroll
            for (int nt = 0; nt < 4; nt++)
                mma_f16(acc[mt][nt], afr, bfr[nt]);
        }
    }
    __syncthreads();

    // ---- relu(acc + b1) back into As as half2 ----
#pragma unroll
    for (int mt = 0; mt < 4; mt++) {
        int r0 = wm * 64 + mt * 16 + gid;
#pragma unroll
        for (int nt = 0; nt < 4; nt++) {
            int c0 = wn * 32 + nt * 8 + 2 * tig;
            float bb0 = __ldg(b1 + c0), bb1 = __ldg(b1 + c0 + 1);
            __half2 v0 = __floats2half2_rn(fmaxf(acc[mt][nt][0] + bb0, 0.f),
                                           fmaxf(acc[mt][nt][1] + bb1, 0.f));
            __half2 v1 = __floats2half2_rn(fmaxf(acc[mt][nt][2] + bb0, 0.f),
                                           fmaxf(acc[mt][nt][3] + bb1, 0.f));
            Asw[r0 * HW + (c0 >> 1)] = *(uint32_t*)&v0;
            Asw[(r0 + 8) * HW + (c0 >> 1)] = *(uint32_t*)&v1;
        }
    }
    // ---- reload Bs = W2 ----
#pragma unroll
    for (int it = 0; it < 8; it++) {
        int idx = tid + it * 256;
        int r = idx >> 4;
        int c8 = idx & 15;
        uint4 vb = __ldg((const uint4*)(W2t + (size_t)r * 128) + c8);
        *(uint4*)&Bs16[r * HS + c8 * 8] = vb;
    }
    __syncthreads();

    // ---- mainloop 2 (W2) ----
#pragma unroll
    for (int mt = 0; mt < 4; mt++)
#pragma unroll
        for (int nt = 0; nt < 4; nt++)
#pragma unroll
            for (int q = 0; q < 4; q++) acc[mt][nt][q] = 0.0f;

#pragma unroll
    for (int ks = 0; ks < 8; ks++) {
        int kw = ks * 8;
        uint32_t bfr[4][2];
#pragma unroll
        for (int nt = 0; nt < 4; nt++) {
            int n = wn * 32 + nt * 8 + gid;
            bfr[nt][0] = Bsw[n * HW + kw + tig];
            bfr[nt][1] = Bsw[n * HW + kw + tig + 4];
        }
#pragma unroll
        for (int mt = 0; mt < 4; mt++) {
            int r = wm * 64 + mt * 16 + gid;
            uint32_t afr[4];
            afr[0] = Asw[r * HW + kw + tig];
            afr[1] = Asw[(r + 8) * HW + kw + tig];
            afr[2] = Asw[r * HW + kw + tig + 4];
            afr[3] = Asw[(r + 8) * HW + kw + tig + 4];
#pragma unroll
            for (int nt = 0; nt < 4; nt++)
                mma_f16(acc[mt][nt], afr, bfr[nt]);
        }
    }

    // ---- epilogue to global (fp32) ----
#pragma unroll
    for (int mt = 0; mt < 4; mt++) {
        int r0 = row0 + wm * 64 + mt * 16 + gid;
        int r1 = r0 + 8;
#pragma unroll
        for (int nt = 0; nt < 4; nt++) {
            int c0 = wn * 32 + nt * 8 + 2 * tig;
            float bb0 = __ldg(b2 + c0), bb1 = __ldg(b2 + c0 + 1);
            float2 v0 = make_float2(acc[mt][nt][0] + bb0, acc[mt][nt][1] + bb1);
            float2 v1 = make_float2(acc[mt][nt][2] + bb0, acc[mt][nt][3] + bb1);
            if (r0 < M) *(float2*)(C + (size_t)r0 * 128 + c0) = v0;
            if (r1 < M) *(float2*)(C + (size_t)r1 * 128 + c0) = v1;
        }
    }
}

// ---------------------------------------------------------------------------
extern "C" void kernel_launch(void* const* d_in, const int* in_sizes, int n_in,
                              void* d_out, int out_size) {
    const float* x   = (const float*)d_in[0];
    const int*   ei  = (const int*)d_in[1];
    const float* W1  = (const float*)d_in[2];
    const float* b1  = (const float*)d_in[3];
    const float* W2  = (const float*)d_in[4];
    const float* b2  = (const float*)d_in[5];
    const float* eps = (const float*)d_in[6];
    float*       out = (float*)d_out;

    const int n_nodes = in_sizes[0] / D;
    const int n_edges = in_sizes[1] / 2;
    const int* src = ei;
    const int* dst = ei + n_edges;

    __half *h0, *w1t, *w2t;
    cudaGetSymbolAddress((void**)&h0, g_h0);
    cudaGetSymbolAddress((void**)&w1t, g_W1t);
    cudaGetSymbolAddress((void**)&w2t, g_W2t);

    const int SMEM = 2 * TM * HS * (int)sizeof(__half);  // 69632
    cudaFuncSetAttribute(fused_mlp_kernel,
                         cudaFuncAttributeMaxDynamicSharedMemorySize, SMEM);

    zero_kernel<<<(n_nodes + 255) / 256, 256>>>(n_nodes);

    int n8 = n_nodes * D / 8;
    int n_conv = (n8 + 255) / 256;
    int n_fill = (n_edges + 255) / 256;
    work_kernel<<<n_conv + n_fill + 32, 256>>>(x, n8, n_conv,
                                               src, dst, n_edges, n_fill,
                                               W1, w1t, W2, w2t);

    int gwarps = (n_nodes * 32 + 255) / 256;
    gather_kernel<<<gwarps, 256>>>(eps, n_nodes);

    int gblocks = (n_nodes + TM - 1) / TM;
    fused_mlp_kernel<<<gblocks, 256, SMEM>>>(h0, w1t, b1, w2t, b2, out, n_nodes);
}